// round 14
// baseline (speedup 1.0000x reference)
#include <cuda_runtime.h>
#include <cuda_fp16.h>
#include <math.h>
#include <stdint.h>

#define LSEQ 2048
#define BATCH 2
#define EMB 512
#define NH 8
#define HD 64
#define NHEAD 16  // BATCH*NH

#define NX (LSEQ * BATCH * EMB)  // 2097152
#define NWI (3 * EMB * EMB)      // 786432
#define NWO (EMB * EMB)          // 262144
#define NER (LSEQ * HD)          // 131072

// interleave-within-16 (fp16 m16n8k16 frags): k -> slot so that thread t4's
// {2t4, 2t4+1, 2t4+8, 2t4+9} are contiguous (one LDS.64). Preserves bit 0.
#define ILV16(d) (((d) & ~15) | ((((d) >> 1) & 3) << 2) | ((((d) >> 3) & 1) << 1) | ((d) & 1))

#define LOG2E 1.4426950408889634f

// Scratch (device globals; allocation-free per harness rules)
__device__ __align__(16) __half g_qh[NHEAD * LSEQ * HD];   // [h][l][d_ILV16], x 0.125*log2e
__device__ __align__(16) __half g_kh[NHEAD * LSEQ * HD];   // [h][l][d_ILV16]
__device__ __align__(16) __half g_vh[NHEAD * LSEQ * HD];   // [h][d][m_ILV16] (transposed)
__device__ __align__(16) __half g_oh[NHEAD * LSEQ * HD];   // [h][l][d_ILV16]
// PRE-SKEWED rel scores: S[h][l][m] = q[l].er[2047-l+m] for 0<=m<=l, else 0
// (zero-initialized device global; m>l region never written).
__device__ __align__(16) __half g_Sh[(size_t)NHEAD * LSEQ * LSEQ + 16];  // 128 MiB
// fp16 ILV16 copies of inputs (K-dims interleaved for mma16 frags)
__device__ __align__(16) __half g_xh[NX];    // [r][e_ILV16]
__device__ __align__(16) __half g_wih[NWI];  // [c][e_ILV16]
__device__ __align__(16) __half g_woh[NWO];  // [c][e_ILV16]
__device__ __align__(16) __half g_erh[NER];  // [m][d_ILV16]

__device__ __forceinline__ uint32_t pack_h2(float lo, float hi) {
    uint32_t r;  // r.lo = cvt(lo), r.hi = cvt(hi)
    asm("cvt.rn.f16x2.f32 %0, %1, %2;" : "=r"(r) : "f"(hi), "f"(lo));
    return r;
}

__device__ __forceinline__ float ex2(float x) {
    float y;
    asm("ex2.approx.f32 %0, %1;" : "=f"(y) : "f"(x));
    return y;
}

__device__ __forceinline__ void mma16(float d[4], uint32_t a0, uint32_t a1,
                                      uint32_t a2, uint32_t a3,
                                      uint32_t b0, uint32_t b1) {
    asm volatile(
        "mma.sync.aligned.m16n8k16.row.col.f32.f16.f16.f32 "
        "{%0,%1,%2,%3}, {%4,%5,%6,%7}, {%8,%9}, {%0,%1,%2,%3};\n"
        : "+f"(d[0]), "+f"(d[1]), "+f"(d[2]), "+f"(d[3])
        : "r"(a0), "r"(a1), "r"(a2), "r"(a3), "r"(b0), "r"(b1));
}

__device__ __forceinline__ void cp16(uint32_t dst, const void* src) {
    asm volatile("cp.async.cg.shared.global [%0], [%1], 16;\n" ::"r"(dst), "l"(src));
}
__device__ __forceinline__ void cp_commit() { asm volatile("cp.async.commit_group;\n"); }
__device__ __forceinline__ void cp_wait0() { asm volatile("cp.async.wait_group 0;\n" ::: "memory"); }
__device__ __forceinline__ void cp_wait1() { asm volatile("cp.async.wait_group 1;\n" ::: "memory"); }

// ---------------------------------------------------------------------------
// Kernel 0: convert inputs to fp16 with ILV16 K-dim interleave.
// ---------------------------------------------------------------------------
__global__ void __launch_bounds__(256) preround(const float4* __restrict__ x,
                                                const float4* __restrict__ Wi,
                                                const float4* __restrict__ Wo,
                                                const float4* __restrict__ Er) {
    int i = blockIdx.x * 256 + threadIdx.x;  // grid sized exactly
    float4 v;
    __half* dst;
    int idx;
    if (i < NX / 4) { v = x[i]; dst = g_xh; idx = i * 4; }
    else if (i < (NX + NWI) / 4) { int j = i - NX / 4; v = Wi[j]; dst = g_wih; idx = j * 4; }
    else if (i < (NX + NWI + NWO) / 4) { int j = i - (NX + NWI) / 4; v = Wo[j]; dst = g_woh; idx = j * 4; }
    else { int j = i - (NX + NWI + NWO) / 4; v = Er[j]; dst = g_erh; idx = j * 4; }
    *(uint32_t*)(dst + ILV16(idx)) = pack_h2(v.x, v.y);
    *(uint32_t*)(dst + ILV16(idx + 2)) = pack_h2(v.z, v.w);
}

// One BK=32 fp16 stage (2 k-groups), smem stride 48 halves. 8 warps 4(m)x2(n).
template <int NF>
__device__ __forceinline__ void gemm16_stage(const __half* A, const __half* B,
                                             float acc[2][NF][4], int wm, int wn,
                                             int rq, int t4) {
#pragma unroll
    for (int g = 0; g < 2; g++) {
        uint2 bf[NF];
#pragma unroll
        for (int nf = 0; nf < NF; nf++)
            bf[nf] = *(const uint2*)(B + (wn * NF * 8 + nf * 8 + rq) * 48 + g * 16 + 4 * t4);
#pragma unroll
        for (int mf = 0; mf < 2; mf++) {
            const __half* ap = A + (wm * 32 + mf * 16 + rq) * 48 + g * 16 + 4 * t4;
            uint2 alo = *(const uint2*)ap;
            uint2 ahi = *(const uint2*)(ap + 8 * 48);
#pragma unroll
            for (int nf = 0; nf < NF; nf++)
                mma16(acc[mf][nf], alo.x, ahi.x, alo.y, ahi.y, bf[nf].x, bf[nf].y);
        }
    }
}

// ---------------------------------------------------------------------------
// Kernel 1: qkv = x @ Wi^T + b -> scatter fp16: q (x 0.125*log2e) / k ILV16,
// v transposed [h][d][m_ILV16]. BM=BN=128, BK=32, fp16 mma16, cp.async x2.
// ---------------------------------------------------------------------------
#define QAH (128 * 48)  // halves per 128-row stage
__global__ void __launch_bounds__(256, 2) gemm_qkv(const float* __restrict__ bias) {
    extern __shared__ __half smq[];
    __half* As = smq;              // [2][128*48]
    __half* Bs = smq + 2 * QAH;    // [2][128*48]
    const int tid = threadIdx.x, lane = tid & 31, warp = tid >> 5;
    const int wm = warp >> 1, wn = warp & 1;
    const int rq = lane >> 2, t4 = lane & 3;
    const int r0 = blockIdx.x * 128, c0 = blockIdx.y * 128;
    uint32_t sA = (uint32_t)__cvta_generic_to_shared(As);
    uint32_t sB = (uint32_t)__cvta_generic_to_shared(Bs);
    float acc[2][8][4] = {};

    auto prefetch = [&](int st, int kt) {
        int k0 = kt * 32;
#pragma unroll
        for (int p = 0; p < 2; p++) {
            int c = tid + p * 256;
            int row = c >> 2, off = c & 3;
            cp16(sA + (st * QAH + row * 48) * 2 + off * 16,
                 g_xh + (size_t)(r0 + row) * EMB + k0 + off * 8);
            cp16(sB + (st * QAH + row * 48) * 2 + off * 16,
                 g_wih + (size_t)(c0 + row) * EMB + k0 + off * 8);
        }
    };

    prefetch(0, 0);
    cp_commit();
    const int nk = EMB / 32;
    for (int kt = 0; kt < nk; kt++) {
        if (kt + 1 < nk) {
            prefetch((kt + 1) & 1, kt + 1);
            cp_commit();
            cp_wait1();
        } else {
            cp_wait0();
        }
        __syncthreads();
        gemm16_stage<8>(As + (kt & 1) * QAH, Bs + (kt & 1) * QAH, acc, wm, wn, rq, t4);
        __syncthreads();
    }

#pragma unroll
    for (int mf = 0; mf < 2; mf++)
#pragma unroll
        for (int nf = 0; nf < 8; nf++)
#pragma unroll
            for (int j = 0; j < 4; j++) {
                int r = r0 + wm * 32 + mf * 16 + rq + (j >> 1) * 8;
                int c = c0 + wn * 64 + nf * 8 + 2 * t4 + (j & 1);
                float val = acc[mf][nf][j] + bias[c];
                int l = r >> 1, b = r & 1;
                int part = c >> 9;
                int cc = c & 511;
                int h = cc >> 6, d = cc & 63;
                int hb = b * NH + h;
                if (part == 0)
                    g_qh[((size_t)hb * LSEQ + l) * HD + ILV16(d)] =
                        __float2half(val * (0.125f * LOG2E));
                else if (part == 1)
                    g_kh[((size_t)hb * LSEQ + l) * HD + ILV16(d)] = __float2half(val);
                else
                    g_vh[((size_t)hb * HD + d) * LSEQ + ILV16(l)] = __float2half(val);
            }
}

// ---------------------------------------------------------------------------
// Kernel 2: computes R[l][c] = q[l].er[c] (log2-domain) and stores it
// PRE-SKEWED: S[h][l][m] with m = c + l - 2047 (predicated m >= 0; m <= l
// holds automatically). Band: l0 + c0 >= 1857 covers the whole written set.
// ---------------------------------------------------------------------------
__global__ void __launch_bounds__(256, 2) gemm_rel() {
    if (128 * blockIdx.x + 64 * blockIdx.y < 1857) return;
    extern __shared__ __half smr[];
    __half* As = smr;              // [128*80]
    __half* Bs = smr + 128 * 80;   // [64*80]
    const int tid = threadIdx.x, lane = tid & 31, warp = tid >> 5;
    const int wm = warp >> 1, wn = warp & 1;
    const int rq = lane >> 2, t4 = lane & 3;
    const int l0 = blockIdx.x * 128, c0 = blockIdx.y * 64;
    const int h = blockIdx.z;
    uint32_t sA = (uint32_t)__cvta_generic_to_shared(As);
    uint32_t sB = (uint32_t)__cvta_generic_to_shared(Bs);

#pragma unroll
    for (int p = 0; p < 4; p++) {
        int c = tid + p * 256;
        int row = c >> 3, off = c & 7;
        cp16(sA + row * 160 + off * 16,
             g_qh + ((size_t)h * LSEQ + l0 + row) * HD + off * 8);
    }
#pragma unroll
    for (int p = 0; p < 2; p++) {
        int c = tid + p * 256;
        int row = c >> 3, off = c & 7;
        cp16(sB + row * 160 + off * 16,
             g_erh + (size_t)(c0 + row) * HD + off * 8);
    }
    cp_commit();
    cp_wait0();
    __syncthreads();

    float acc[2][4][4] = {};
#pragma unroll
    for (int g = 0; g < 4; g++) {
        uint2 bf[4];
#pragma unroll
        for (int nf = 0; nf < 4; nf++)
            bf[nf] = *(const uint2*)(Bs + (wn * 32 + nf * 8 + rq) * 80 + g * 16 + 4 * t4);
#pragma unroll
        for (int mf = 0; mf < 2; mf++) {
            const __half* ap = As + (wm * 32 + mf * 16 + rq) * 80 + g * 16 + 4 * t4;
            uint2 alo = *(const uint2*)ap;
            uint2 ahi = *(const uint2*)(ap + 8 * 80);
#pragma unroll
            for (int nf = 0; nf < 4; nf++)
                mma16(acc[mf][nf], alo.x, ahi.x, alo.y, ahi.y, bf[nf].x, bf[nf].y);
        }
    }

    // skewed scatter store: S[l][c + l - 2047] (U16 per element, m>=0 only)
#pragma unroll
    for (int mf = 0; mf < 2; mf++)
#pragma unroll
        for (int nf = 0; nf < 4; nf++)
#pragma unroll
            for (int jj = 0; jj < 2; jj++) {
                int l = l0 + wm * 32 + mf * 16 + rq + jj * 8;
                int c = c0 + wn * 32 + nf * 8 + 2 * t4;
                int m = c + l - 2047;
                __half* Srow = g_Sh + ((size_t)h * LSEQ + l) * LSEQ;
                if (m >= 0) Srow[m] = __float2half(acc[mf][nf][jj * 2]);
                if (m + 1 >= 0) Srow[m + 1] = __float2half(acc[mf][nf][jj * 2 + 1]);
            }
}

// ---------------------------------------------------------------------------
// Kernel 3: fused flash attention + pre-skewed rel add (fp16 mma16, log2-
// domain scores -> ex2). BM=128 (8 warps x 16 rows), BN=128 per iteration as
// two 64-key sub-tiles; 2-stage cp.async; ONE barrier per 128 keys.
// Rel add: unconditional aligned LDG.32 pairs from S[l][m] (zeros above diag).
// PV as O^T = V^T @ P^T with B-frags = packed QK C-frags (zero movement).
// ---------------------------------------------------------------------------
#define KST_B 160        // bytes per smem row (64 halves data + pad)
#define TILE_B 10240     // one 64-key K or V sub-tile
#define SUB_B 20480      // K+V for one 64-key sub-tile
#define STAGE_B 40960    // 128 keys (two sub-tiles)
#define Q_B 81920        // Q region offset (2 stages * STAGE_B)
#define FLASH_SMEM (Q_B + 128 * KST_B)  // 102400 B
__global__ void __launch_bounds__(256, 2) flash_attn() {
    extern __shared__ char smc[];
    const int tid = threadIdx.x, lane = tid & 31, warp = tid >> 5;
    const int rq = lane >> 2, t4 = lane & 3;
    const int h = blockIdx.y;
    const int l0 = blockIdx.x * 128;
    const __half* qg = g_qh + (size_t)h * LSEQ * HD;
    const __half* kg = g_kh + (size_t)h * LSEQ * HD;
    const __half* vg = g_vh + (size_t)h * HD * LSEQ;  // [d][m_ILV16]
    uint32_t sb = (uint32_t)__cvta_generic_to_shared(smc);

    // stage Q (128 rows x 128 B) into its own region
#pragma unroll
    for (int p = 0; p < 4; p++) {
        int cg = tid + p * 256;
        int row = cg >> 3, off = cg & 7;
        cp16(sb + Q_B + row * KST_B + off * 16, qg + (size_t)(l0 + row) * HD + off * 8);
    }
    cp_commit();

    // one stage = 128 keys: [K0 | V0 | K1 | V1]
    auto pre_stage = [&](int st, int kt2) {
#pragma unroll
        for (int sub = 0; sub < 2; sub++) {
            int m0 = kt2 * 128 + sub * 64;
            uint32_t base = sb + st * STAGE_B + sub * SUB_B;
#pragma unroll
            for (int p = 0; p < 2; p++) {
                int cg = tid + p * 256;
                int row = cg >> 3, off = cg & 7;
                cp16(base + row * KST_B + off * 16,
                     kg + (size_t)(m0 + row) * HD + off * 8);
                cp16(base + TILE_B + row * KST_B + off * 16,
                     vg + (size_t)row * LSEQ + m0 + off * 8);
            }
        }
    };
    pre_stage(0, 0);
    cp_commit();

    cp_wait0();
    __syncthreads();

    // Q fragments -> registers
    uint32_t qf[4][4];
    {
        const __half* qrow = (const __half*)(smc + Q_B) + (warp * 16 + rq) * 80;
#pragma unroll
        for (int g = 0; g < 4; g++) {
            uint2 lo = *(const uint2*)(qrow + g * 16 + 4 * t4);
            uint2 hi = *(const uint2*)(qrow + 8 * 80 + g * 16 + 4 * t4);
            qf[g][0] = lo.x;
            qf[g][1] = hi.x;
            qf[g][2] = lo.y;
            qf[g][3] = hi.y;
        }
    }

    const int row_lo = warp * 16 + rq;
    float lsum[2] = {0.f, 0.f};
    float ot[4][2][4] = {};  // O^T accum: [d-frag mf][l-frag nf][c]

    for (int kt2 = 0; kt2 < 16; kt2++) {
        cp_wait0();        // stage kt2 resident (loaded during previous iter)
        __syncthreads();   // visible to all; other slot's readers done
        if (kt2 + 1 < 16) {
            pre_stage((kt2 + 1) & 1, kt2 + 1);
            cp_commit();
        }
        const char* stg = smc + (kt2 & 1) * STAGE_B;

#pragma unroll
        for (int sub = 0; sub < 2; sub++) {
            const int m0 = kt2 * 128 + sub * 64;
            const __half* K = (const __half*)(stg + sub * SUB_B);
            const __half* V = (const __half*)(stg + sub * SUB_B + TILE_B);

            // S = Q @ K^T  (scores already in log2 domain via q scaling)
            float s[8][4] = {};
#pragma unroll
            for (int g = 0; g < 4; g++) {
#pragma unroll
                for (int nc = 0; nc < 8; nc++) {
                    uint2 b = *(const uint2*)(K + (nc * 8 + rq) * 80 + g * 16 + 4 * t4);
                    mma16(s[nc], qf[g][0], qf[g][1], qf[g][2], qf[g][3], b.x, b.y);
                }
            }

            // + pre-skewed rel scores: unconditional aligned pair loads
            // (S[l][m] is zero for m > l, so no predicates needed)
            if (m0 <= l0 + 127) {
#pragma unroll
                for (int i = 0; i < 2; i++) {
                    int l = l0 + row_lo + i * 8;
                    const __half* Srow = g_Sh + ((size_t)h * LSEQ + l) * LSEQ + m0;
#pragma unroll
                    for (int nc = 0; nc < 8; nc++) {
                        uint32_t pr = *(const uint32_t*)(Srow + nc * 8 + 2 * t4);
                        __half2 h2 = *(__half2*)&pr;
                        s[nc][2 * i] += __low2float(h2);
                        s[nc][2 * i + 1] += __high2float(h2);
                    }
                }
            }

            // p = 2^s in place (bounded scores; no max tracking)
#pragma unroll
            for (int nc = 0; nc < 8; nc++) {
#pragma unroll
                for (int j = 0; j < 4; j++) {
                    float p = ex2(s[nc][j]);
                    s[nc][j] = p;
                    lsum[j >> 1] += p;
                }
            }

            // O^T += V^T @ P^T : A from V^T (LDS.64), B = packed C-frags
#pragma unroll
            for (int g = 0; g < 4; g++) {
                uint32_t b0a = pack_h2(s[2 * g][0], s[2 * g][1]);
                uint32_t b1a = pack_h2(s[2 * g + 1][0], s[2 * g + 1][1]);
                uint32_t b0b = pack_h2(s[2 * g][2], s[2 * g][3]);
                uint32_t b1b = pack_h2(s[2 * g + 1][2], s[2 * g + 1][3]);
#pragma unroll
                for (int mf = 0; mf < 4; mf++) {
                    const __half* vp = V + (mf * 16 + rq) * 80 + g * 16 + 4 * t4;
                    uint2 lo = *(const uint2*)vp;
                    uint2 hi = *(const uint2*)(vp + 8 * 80);
                    mma16(ot[mf][0], lo.x, hi.x, lo.y, hi.y, b0a, b1a);
                    mma16(ot[mf][1], lo.x, hi.x, lo.y, hi.y, b0b, b1b);
                }
            }
        }
    }
    __syncthreads();  // all tile reads done before slab reuse of stage smem

    // Si: quad-reduce thread partials
#pragma unroll
    for (int off = 1; off < 4; off <<= 1) {
        lsum[0] += __shfl_xor_sync(0xffffffffu, lsum[0], off);
        lsum[1] += __shfl_xor_sync(0xffffffffu, lsum[1], off);
    }
    float SiA = __shfl_sync(0xffffffffu, lsum[0], (2 * t4) << 2);
    float SiB = __shfl_sync(0xffffffffu, lsum[0], ((2 * t4 + 1) << 2));
    float SiC = __shfl_sync(0xffffffffu, lsum[1], (2 * t4) << 2);
    float SiD = __shfl_sync(0xffffffffu, lsum[1], ((2 * t4 + 1) << 2));
    float invA = 1.0f / SiA, invB = 1.0f / SiB;
    float invC = 1.0f / SiC, invD = 1.0f / SiD;

    // Epilogue: normalize + transpose via per-warp fp32 slab (stride 68),
    // then fp16 ILV16 stores to g_oh (pairs adjacent, uint32 stores).
    float* slab = (float*)smc + warp * 16 * 68;  // 8 * 4352 B = 34816 B
#pragma unroll
    for (int mf = 0; mf < 4; mf++)
#pragma unroll
        for (int nf = 0; nf < 2; nf++)
#pragma unroll
            for (int j = 0; j < 4; j++) {
                int ll = nf * 8 + 2 * t4 + (j & 1);
                int d = mf * 16 + rq + (j >> 1) * 8;
                float inv = (nf == 0) ? ((j & 1) ? invB : invA)
                                      : ((j & 1) ? invD : invC);
                slab[ll * 68 + d] = ot[mf][nf][j] * inv;
            }
    __syncwarp();
    {
        int ll = lane >> 1, d0 = (lane & 1) * 32;
        __half* dst = g_oh + ((size_t)h * LSEQ + l0 + warp * 16 + ll) * HD;
#pragma unroll
        for (int u = 0; u < 8; u++) {
            float4 v4 = *(const float4*)(slab + ll * 68 + d0 + u * 4);
            int d = d0 + u * 4;
            *(uint32_t*)(dst + ILV16(d)) = pack_h2(v4.x, v4.y);
            *(uint32_t*)(dst + ILV16(d + 2)) = pack_h2(v4.z, v4.w);
        }
    }
}

// ---------------------------------------------------------------------------
// Kernel 4: out = attn_out @ Wo^T + b (fp16 in, fp32 out). BM=128, BN=64.
// ---------------------------------------------------------------------------
#define OAH (128 * 48)
#define OBH (64 * 48)
__global__ void __launch_bounds__(256, 2) gemm_out(const float* __restrict__ bout,
                                                   float* __restrict__ out) {
    extern __shared__ __half smo[];
    __half* As = smo;               // [2][128*48]
    __half* Bs = smo + 2 * OAH;     // [2][64*48]
    const int tid = threadIdx.x, lane = tid & 31, warp = tid >> 5;
    const int wm = warp >> 1, wn = warp & 1;
    const int rq = lane >> 2, t4 = lane & 3;
    const int r0 = blockIdx.x * 128, c0 = blockIdx.y * 64;
    uint32_t sA = (uint32_t)__cvta_generic_to_shared(As);
    uint32_t sB = (uint32_t)__cvta_generic_to_shared(Bs);
    float acc[2][4][4] = {};

    auto prefetch = [&](int st, int kt) {
        int k0 = kt * 32;
#pragma unroll
        for (int p = 0; p < 2; p++) {
            int c = tid + p * 256;
            int row = c >> 2, off = c & 3;
            int r = r0 + row;
            int l = r >> 1, b = r & 1;
            int e = k0 + off * 8;
            int hh = e >> 6, d = e & 63;
            cp16(sA + (st * OAH + row * 48) * 2 + off * 16,
                 g_oh + ((size_t)(b * NH + hh) * LSEQ + l) * HD + d);
        }
        {
            int row = tid >> 2, off = tid & 3;
            cp16(sB + (st * OBH + row * 48) * 2 + off * 16,
                 g_woh + (size_t)(c0 + row) * EMB + k0 + off * 8);
        }
    };

    prefetch(0, 0);
    cp_commit();
    const int nk = EMB / 32;
    for (int kt = 0; kt < nk; kt++) {
        if (kt + 1 < nk) {
            prefetch((kt + 1) & 1, kt + 1);
            cp_commit();
            cp_wait1();
        } else {
            cp_wait0();
        }
        __syncthreads();
        gemm16_stage<4>(As + (kt & 1) * OAH, Bs + (kt & 1) * OBH, acc, wm, wn, rq, t4);
        __syncthreads();
    }

#pragma unroll
    for (int mf = 0; mf < 2; mf++)
#pragma unroll
        for (int nf = 0; nf < 4; nf++)
#pragma unroll
            for (int j = 0; j < 4; j++) {
                int r = r0 + wm * 32 + mf * 16 + rq + (j >> 1) * 8;
                int c = c0 + wn * 32 + nf * 8 + 2 * t4 + (j & 1);
                out[(size_t)r * EMB + c] = acc[mf][nf][j] + bout[c];
            }
}

// ---------------------------------------------------------------------------
extern "C" void kernel_launch(void* const* d_in, const int* in_sizes, int n_in,
                              void* d_out, int out_size) {
    (void)in_sizes; (void)n_in; (void)out_size;
    const float* x    = (const float*)d_in[0];
    const float* Win  = (const float*)d_in[1];
    const float* bin  = (const float*)d_in[2];
    const float* Wout = (const float*)d_in[3];
    const float* bout = (const float*)d_in[4];
    const float* Er   = (const float*)d_in[5];
    float* out = (float*)d_out;

    const int qkv_smem = 4 * QAH * sizeof(__half);                 // 49152
    const int rel_smem = (128 + 64) * 80 * sizeof(__half);         // 30720
    const int out_smem = (2 * OAH + 2 * OBH) * sizeof(__half);     // 36864

    cudaFuncSetAttribute(gemm_qkv, cudaFuncAttributeMaxDynamicSharedMemorySize, qkv_smem);
    cudaFuncSetAttribute(gemm_rel, cudaFuncAttributeMaxDynamicSharedMemorySize, rel_smem);
    cudaFuncSetAttribute(gemm_out, cudaFuncAttributeMaxDynamicSharedMemorySize, out_smem);
    cudaFuncSetAttribute(flash_attn, cudaFuncAttributeMaxDynamicSharedMemorySize, FLASH_SMEM);

    preround<<<(NX + NWI + NWO + NER) / 4 / 256, 256>>>(
        (const float4*)x, (const float4*)Win, (const float4*)Wout, (const float4*)Er);
    gemm_qkv<<<dim3(32, 12), 256, qkv_smem>>>(bin);
    gemm_rel<<<dim3(16, 32, 16), 256, rel_smem>>>();
    flash_attn<<<dim3(16, 16), 256, FLASH_SMEM>>>();
    gemm_out<<<dim3(32, 8), 256, out_smem>>>(bout, out);
}

// round 15
// speedup vs baseline: 1.1642x; 1.1642x over previous
#include <cuda_runtime.h>
#include <cuda_fp16.h>
#include <math.h>
#include <stdint.h>

#define LSEQ 2048
#define BATCH 2
#define EMB 512
#define NH 8
#define HD 64
#define NHEAD 16  // BATCH*NH

#define NX (LSEQ * BATCH * EMB)  // 2097152
#define NWI (3 * EMB * EMB)      // 786432
#define NWO (EMB * EMB)          // 262144
#define NER (LSEQ * HD)          // 131072

// interleave-within-16 (fp16 m16n8k16 frags): k -> slot so that thread t4's
// {2t4, 2t4+1, 2t4+8, 2t4+9} are contiguous (one LDS.64). Preserves bit 0.
#define ILV16(d) (((d) & ~15) | ((((d) >> 1) & 3) << 2) | ((((d) >> 3) & 1) << 1) | ((d) & 1))

#define LOG2E 1.4426950408889634f

// Scratch (device globals; allocation-free per harness rules)
__device__ __align__(16) __half g_qh[NHEAD * LSEQ * HD];   // [h][l][d_ILV16], x 0.125*log2e
__device__ __align__(16) __half g_kh[NHEAD * LSEQ * HD];   // [h][l][d_ILV16]
__device__ __align__(16) __half g_vh[NHEAD * LSEQ * HD];   // [h][d][m_ILV16] (transposed)
__device__ __align__(16) __half g_oh[NHEAD * LSEQ * HD];   // [h][l][d_ILV16]
// PRE-SKEWED rel scores: S[h][l][m] = q[l].er[2047-l+m] for 0<=m<=l, else 0
// (zero-initialized device global; m>l region never written).
__device__ __align__(16) __half g_Sh[(size_t)NHEAD * LSEQ * LSEQ + 16];  // 128 MiB
// fp16 ILV16 copies of inputs (K-dims interleaved for mma16 frags)
__device__ __align__(16) __half g_xh[NX];    // [r][e_ILV16]
__device__ __align__(16) __half g_wih[NWI];  // [c][e_ILV16]
__device__ __align__(16) __half g_woh[NWO];  // [c][e_ILV16]
__device__ __align__(16) __half g_erh[NER];  // [m][d_ILV16]

__device__ __forceinline__ uint32_t pack_h2(float lo, float hi) {
    uint32_t r;  // r.lo = cvt(lo), r.hi = cvt(hi)
    asm("cvt.rn.f16x2.f32 %0, %1, %2;" : "=r"(r) : "f"(hi), "f"(lo));
    return r;
}

__device__ __forceinline__ float ex2(float x) {
    float y;
    asm("ex2.approx.f32 %0, %1;" : "=f"(y) : "f"(x));
    return y;
}

__device__ __forceinline__ void mma16(float d[4], uint32_t a0, uint32_t a1,
                                      uint32_t a2, uint32_t a3,
                                      uint32_t b0, uint32_t b1) {
    asm volatile(
        "mma.sync.aligned.m16n8k16.row.col.f32.f16.f16.f32 "
        "{%0,%1,%2,%3}, {%4,%5,%6,%7}, {%8,%9}, {%0,%1,%2,%3};\n"
        : "+f"(d[0]), "+f"(d[1]), "+f"(d[2]), "+f"(d[3])
        : "r"(a0), "r"(a1), "r"(a2), "r"(a3), "r"(b0), "r"(b1));
}

__device__ __forceinline__ void cp16(uint32_t dst, const void* src) {
    asm volatile("cp.async.cg.shared.global [%0], [%1], 16;\n" ::"r"(dst), "l"(src));
}
__device__ __forceinline__ void cp_commit() { asm volatile("cp.async.commit_group;\n"); }
__device__ __forceinline__ void cp_wait0() { asm volatile("cp.async.wait_group 0;\n" ::: "memory"); }
__device__ __forceinline__ void cp_wait1() { asm volatile("cp.async.wait_group 1;\n" ::: "memory"); }

// ---------------------------------------------------------------------------
// Kernel 0: convert inputs to fp16 with ILV16 K-dim interleave.
// ---------------------------------------------------------------------------
__global__ void __launch_bounds__(256) preround(const float4* __restrict__ x,
                                                const float4* __restrict__ Wi,
                                                const float4* __restrict__ Wo,
                                                const float4* __restrict__ Er) {
    int i = blockIdx.x * 256 + threadIdx.x;  // grid sized exactly
    float4 v;
    __half* dst;
    int idx;
    if (i < NX / 4) { v = x[i]; dst = g_xh; idx = i * 4; }
    else if (i < (NX + NWI) / 4) { int j = i - NX / 4; v = Wi[j]; dst = g_wih; idx = j * 4; }
    else if (i < (NX + NWI + NWO) / 4) { int j = i - (NX + NWI) / 4; v = Wo[j]; dst = g_woh; idx = j * 4; }
    else { int j = i - (NX + NWI + NWO) / 4; v = Er[j]; dst = g_erh; idx = j * 4; }
    *(uint32_t*)(dst + ILV16(idx)) = pack_h2(v.x, v.y);
    *(uint32_t*)(dst + ILV16(idx + 2)) = pack_h2(v.z, v.w);
}

// One BK=32 fp16 stage (2 k-groups), smem stride 48 halves. 8 warps 4(m)x2(n).
template <int NF>
__device__ __forceinline__ void gemm16_stage(const __half* A, const __half* B,
                                             float acc[2][NF][4], int wm, int wn,
                                             int rq, int t4) {
#pragma unroll
    for (int g = 0; g < 2; g++) {
        uint2 bf[NF];
#pragma unroll
        for (int nf = 0; nf < NF; nf++)
            bf[nf] = *(const uint2*)(B + (wn * NF * 8 + nf * 8 + rq) * 48 + g * 16 + 4 * t4);
#pragma unroll
        for (int mf = 0; mf < 2; mf++) {
            const __half* ap = A + (wm * 32 + mf * 16 + rq) * 48 + g * 16 + 4 * t4;
            uint2 alo = *(const uint2*)ap;
            uint2 ahi = *(const uint2*)(ap + 8 * 48);
#pragma unroll
            for (int nf = 0; nf < NF; nf++)
                mma16(acc[mf][nf], alo.x, ahi.x, alo.y, ahi.y, bf[nf].x, bf[nf].y);
        }
    }
}

// ---------------------------------------------------------------------------
// Kernel 1: qkv = x @ Wi^T + b -> scatter fp16: q (x 0.125*log2e) / k ILV16,
// v transposed [h][d][m_ILV16]. BM=BN=128, BK=32, fp16 mma16, cp.async x2.
// ---------------------------------------------------------------------------
#define QAH (128 * 48)  // halves per 128-row stage
__global__ void __launch_bounds__(256, 2) gemm_qkv(const float* __restrict__ bias) {
    extern __shared__ __half smq[];
    __half* As = smq;              // [2][128*48]
    __half* Bs = smq + 2 * QAH;    // [2][128*48]
    const int tid = threadIdx.x, lane = tid & 31, warp = tid >> 5;
    const int wm = warp >> 1, wn = warp & 1;
    const int rq = lane >> 2, t4 = lane & 3;
    const int r0 = blockIdx.x * 128, c0 = blockIdx.y * 128;
    uint32_t sA = (uint32_t)__cvta_generic_to_shared(As);
    uint32_t sB = (uint32_t)__cvta_generic_to_shared(Bs);
    float acc[2][8][4] = {};

    auto prefetch = [&](int st, int kt) {
        int k0 = kt * 32;
#pragma unroll
        for (int p = 0; p < 2; p++) {
            int c = tid + p * 256;
            int row = c >> 2, off = c & 3;
            cp16(sA + (st * QAH + row * 48) * 2 + off * 16,
                 g_xh + (size_t)(r0 + row) * EMB + k0 + off * 8);
            cp16(sB + (st * QAH + row * 48) * 2 + off * 16,
                 g_wih + (size_t)(c0 + row) * EMB + k0 + off * 8);
        }
    };

    prefetch(0, 0);
    cp_commit();
    const int nk = EMB / 32;
    for (int kt = 0; kt < nk; kt++) {
        if (kt + 1 < nk) {
            prefetch((kt + 1) & 1, kt + 1);
            cp_commit();
            cp_wait1();
        } else {
            cp_wait0();
        }
        __syncthreads();
        gemm16_stage<8>(As + (kt & 1) * QAH, Bs + (kt & 1) * QAH, acc, wm, wn, rq, t4);
        __syncthreads();
    }

#pragma unroll
    for (int mf = 0; mf < 2; mf++)
#pragma unroll
        for (int nf = 0; nf < 8; nf++)
#pragma unroll
            for (int j = 0; j < 4; j++) {
                int r = r0 + wm * 32 + mf * 16 + rq + (j >> 1) * 8;
                int c = c0 + wn * 64 + nf * 8 + 2 * t4 + (j & 1);
                float val = acc[mf][nf][j] + bias[c];
                int l = r >> 1, b = r & 1;
                int part = c >> 9;
                int cc = c & 511;
                int h = cc >> 6, d = cc & 63;
                int hb = b * NH + h;
                if (part == 0)
                    g_qh[((size_t)hb * LSEQ + l) * HD + ILV16(d)] =
                        __float2half(val * (0.125f * LOG2E));
                else if (part == 1)
                    g_kh[((size_t)hb * LSEQ + l) * HD + ILV16(d)] = __float2half(val);
                else
                    g_vh[((size_t)hb * HD + d) * LSEQ + ILV16(l)] = __float2half(val);
            }
}

// ---------------------------------------------------------------------------
// Kernel 2: computes R[l][c] = q[l].er[c] (log2-domain) and stores it
// PRE-SKEWED to S[h][l][m], m = c + l - 2047. Parity fix: stage tile in smem
// with per-row shift e = (c0+l+1)&1 so global-aligned u32 pairs are also
// smem-aligned; then warp-per-row coalesced STG.32 stream (plus U16 edges).
// Band: l0 + c0 >= 1857 covers the whole written set.
// ---------------------------------------------------------------------------
__global__ void __launch_bounds__(256, 2) gemm_rel() {
    if (128 * blockIdx.x + 64 * blockIdx.y < 1857) return;
    extern __shared__ __half smr[];
    __half* As = smr;              // [128*80]
    __half* Bs = smr + 128 * 80;   // [64*80]
    __half* Ss = smr;              // reuse A region after mma: [128][72]
    const int tid = threadIdx.x, lane = tid & 31, warp = tid >> 5;
    const int wm = warp >> 1, wn = warp & 1;
    const int rq = lane >> 2, t4 = lane & 3;
    const int l0 = blockIdx.x * 128, c0 = blockIdx.y * 64;
    const int h = blockIdx.z;
    uint32_t sA = (uint32_t)__cvta_generic_to_shared(As);
    uint32_t sB = (uint32_t)__cvta_generic_to_shared(Bs);

#pragma unroll
    for (int p = 0; p < 4; p++) {
        int c = tid + p * 256;
        int row = c >> 3, off = c & 7;
        cp16(sA + row * 160 + off * 16,
             g_qh + ((size_t)h * LSEQ + l0 + row) * HD + off * 8);
    }
#pragma unroll
    for (int p = 0; p < 2; p++) {
        int c = tid + p * 256;
        int row = c >> 3, off = c & 7;
        cp16(sB + row * 160 + off * 16,
             g_erh + (size_t)(c0 + row) * HD + off * 8);
    }
    cp_commit();
    cp_wait0();
    __syncthreads();

    float acc[2][4][4] = {};
#pragma unroll
    for (int g = 0; g < 4; g++) {
        uint2 bf[4];
#pragma unroll
        for (int nf = 0; nf < 4; nf++)
            bf[nf] = *(const uint2*)(Bs + (wn * 32 + nf * 8 + rq) * 80 + g * 16 + 4 * t4);
#pragma unroll
        for (int mf = 0; mf < 2; mf++) {
            const __half* ap = As + (wm * 32 + mf * 16 + rq) * 80 + g * 16 + 4 * t4;
            uint2 alo = *(const uint2*)ap;
            uint2 ahi = *(const uint2*)(ap + 8 * 80);
#pragma unroll
            for (int nf = 0; nf < 4; nf++)
                mma16(acc[mf][nf], alo.x, ahi.x, alo.y, ahi.y, bf[nf].x, bf[nf].y);
        }
    }
    __syncthreads();  // all mma reads of As/Bs done; A region reusable

    // stage tile into Ss with per-row parity shift
#pragma unroll
    for (int mf = 0; mf < 2; mf++)
#pragma unroll
        for (int nf = 0; nf < 4; nf++)
#pragma unroll
            for (int jj = 0; jj < 2; jj++) {
                int r = wm * 32 + mf * 16 + rq + jj * 8;
                int e = (c0 + l0 + r + 1) & 1;  // = (c0 + l - 2047) & 1
                int col = wn * 32 + nf * 8 + 2 * t4 + e;
                Ss[r * 72 + col] = __float2half(acc[mf][nf][jj * 2]);
                Ss[r * 72 + col + 1] = __float2half(acc[mf][nf][jj * 2 + 1]);
            }
    __syncthreads();

    // coalesced skewed store: one warp per row, 32 aligned STG.32 + edges
    for (int r = warp; r < 128; r += 8) {
        int l = l0 + r;
        int mstart = c0 + l - 2047;   // may be negative at band edge
        int e = mstart & 1;
        int a0 = mstart + e;          // even (aligned) start
        __half* drow = g_Sh + ((size_t)h * LSEQ + l) * LSEQ;
        const __half* srow = Ss + r * 72;
        int idx = a0 + 2 * lane;
        if (lane < 32 - e && idx >= 0)
            *(uint32_t*)(drow + idx) = *(const uint32_t*)(srow + 2 * (lane + e));
        if (e) {
            if (lane == 0 && mstart >= 0) drow[mstart] = srow[1];
            if (lane == 1) drow[mstart + 63] = srow[64];
        }
    }
}

// ---------------------------------------------------------------------------
// Kernel 3: fused flash attention + pre-skewed rel add (fp16 mma16, log2-
// domain scores -> ex2). BM=128 (8 warps x 16 rows), BN=128 per iteration as
// two 64-key sub-tiles; 2-stage cp.async; ONE barrier per 128 keys.
// Rel add: unconditional aligned LDG.32 pairs from S[l][m] (zeros above diag).
// PV as O^T = V^T @ P^T with B-frags = packed QK C-frags (zero movement).
// ---------------------------------------------------------------------------
#define KST_B 160        // bytes per smem row (64 halves data + pad)
#define TILE_B 10240     // one 64-key K or V sub-tile
#define SUB_B 20480      // K+V for one 64-key sub-tile
#define STAGE_B 40960    // 128 keys (two sub-tiles)
#define Q_B 81920        // Q region offset (2 stages * STAGE_B)
#define FLASH_SMEM (Q_B + 128 * KST_B)  // 102400 B
__global__ void __launch_bounds__(256, 2) flash_attn() {
    extern __shared__ char smc[];
    const int tid = threadIdx.x, lane = tid & 31, warp = tid >> 5;
    const int rq = lane >> 2, t4 = lane & 3;
    const int h = blockIdx.y;
    const int l0 = blockIdx.x * 128;
    const __half* qg = g_qh + (size_t)h * LSEQ * HD;
    const __half* kg = g_kh + (size_t)h * LSEQ * HD;
    const __half* vg = g_vh + (size_t)h * HD * LSEQ;  // [d][m_ILV16]
    uint32_t sb = (uint32_t)__cvta_generic_to_shared(smc);

    // stage Q (128 rows x 128 B) into its own region
#pragma unroll
    for (int p = 0; p < 4; p++) {
        int cg = tid + p * 256;
        int row = cg >> 3, off = cg & 7;
        cp16(sb + Q_B + row * KST_B + off * 16, qg + (size_t)(l0 + row) * HD + off * 8);
    }
    cp_commit();

    // one stage = 128 keys: [K0 | V0 | K1 | V1]
    auto pre_stage = [&](int st, int kt2) {
#pragma unroll
        for (int sub = 0; sub < 2; sub++) {
            int m0 = kt2 * 128 + sub * 64;
            uint32_t base = sb + st * STAGE_B + sub * SUB_B;
#pragma unroll
            for (int p = 0; p < 2; p++) {
                int cg = tid + p * 256;
                int row = cg >> 3, off = cg & 7;
                cp16(base + row * KST_B + off * 16,
                     kg + (size_t)(m0 + row) * HD + off * 8);
                cp16(base + TILE_B + row * KST_B + off * 16,
                     vg + (size_t)row * LSEQ + m0 + off * 8);
            }
        }
    };
    pre_stage(0, 0);
    cp_commit();

    cp_wait0();
    __syncthreads();

    // Q fragments -> registers
    uint32_t qf[4][4];
    {
        const __half* qrow = (const __half*)(smc + Q_B) + (warp * 16 + rq) * 80;
#pragma unroll
        for (int g = 0; g < 4; g++) {
            uint2 lo = *(const uint2*)(qrow + g * 16 + 4 * t4);
            uint2 hi = *(const uint2*)(qrow + 8 * 80 + g * 16 + 4 * t4);
            qf[g][0] = lo.x;
            qf[g][1] = hi.x;
            qf[g][2] = lo.y;
            qf[g][3] = hi.y;
        }
    }

    const int row_lo = warp * 16 + rq;
    float lsum[2] = {0.f, 0.f};
    float ot[4][2][4] = {};  // O^T accum: [d-frag mf][l-frag nf][c]

    for (int kt2 = 0; kt2 < 16; kt2++) {
        cp_wait0();        // stage kt2 resident (loaded during previous iter)
        __syncthreads();   // visible to all; other slot's readers done
        if (kt2 + 1 < 16) {
            pre_stage((kt2 + 1) & 1, kt2 + 1);
            cp_commit();
        }
        const char* stg = smc + (kt2 & 1) * STAGE_B;

#pragma unroll
        for (int sub = 0; sub < 2; sub++) {
            const int m0 = kt2 * 128 + sub * 64;
            const __half* K = (const __half*)(stg + sub * SUB_B);
            const __half* V = (const __half*)(stg + sub * SUB_B + TILE_B);

            // S = Q @ K^T  (scores already in log2 domain via q scaling)
            float s[8][4] = {};
#pragma unroll
            for (int g = 0; g < 4; g++) {
#pragma unroll
                for (int nc = 0; nc < 8; nc++) {
                    uint2 b = *(const uint2*)(K + (nc * 8 + rq) * 80 + g * 16 + 4 * t4);
                    mma16(s[nc], qf[g][0], qf[g][1], qf[g][2], qf[g][3], b.x, b.y);
                }
            }

            // + pre-skewed rel scores: unconditional aligned pair loads
            // (S[l][m] is zero for m > l, so no predicates needed)
            if (m0 <= l0 + 127) {
#pragma unroll
                for (int i = 0; i < 2; i++) {
                    int l = l0 + row_lo + i * 8;
                    const __half* Srow = g_Sh + ((size_t)h * LSEQ + l) * LSEQ + m0;
#pragma unroll
                    for (int nc = 0; nc < 8; nc++) {
                        uint32_t pr = *(const uint32_t*)(Srow + nc * 8 + 2 * t4);
                        __half2 h2 = *(__half2*)&pr;
                        s[nc][2 * i] += __low2float(h2);
                        s[nc][2 * i + 1] += __high2float(h2);
                    }
                }
            }

            // p = 2^s in place (bounded scores; no max tracking)
#pragma unroll
            for (int nc = 0; nc < 8; nc++) {
#pragma unroll
                for (int j = 0; j < 4; j++) {
                    float p = ex2(s[nc][j]);
                    s[nc][j] = p;
                    lsum[j >> 1] += p;
                }
            }

            // O^T += V^T @ P^T : A from V^T (LDS.64), B = packed C-frags
#pragma unroll
            for (int g = 0; g < 4; g++) {
                uint32_t b0a = pack_h2(s[2 * g][0], s[2 * g][1]);
                uint32_t b1a = pack_h2(s[2 * g + 1][0], s[2 * g + 1][1]);
                uint32_t b0b = pack_h2(s[2 * g][2], s[2 * g][3]);
                uint32_t b1b = pack_h2(s[2 * g + 1][2], s[2 * g + 1][3]);
#pragma unroll
                for (int mf = 0; mf < 4; mf++) {
                    const __half* vp = V + (mf * 16 + rq) * 80 + g * 16 + 4 * t4;
                    uint2 lo = *(const uint2*)vp;
                    uint2 hi = *(const uint2*)(vp + 8 * 80);
                    mma16(ot[mf][0], lo.x, hi.x, lo.y, hi.y, b0a, b1a);
                    mma16(ot[mf][1], lo.x, hi.x, lo.y, hi.y, b0b, b1b);
                }
            }
        }
    }
    __syncthreads();  // all tile reads done before slab reuse of stage smem

    // Si: quad-reduce thread partials
#pragma unroll
    for (int off = 1; off < 4; off <<= 1) {
        lsum[0] += __shfl_xor_sync(0xffffffffu, lsum[0], off);
        lsum[1] += __shfl_xor_sync(0xffffffffu, lsum[1], off);
    }
    float SiA = __shfl_sync(0xffffffffu, lsum[0], (2 * t4) << 2);
    float SiB = __shfl_sync(0xffffffffu, lsum[0], ((2 * t4 + 1) << 2));
    float SiC = __shfl_sync(0xffffffffu, lsum[1], (2 * t4) << 2);
    float SiD = __shfl_sync(0xffffffffu, lsum[1], ((2 * t4 + 1) << 2));
    float invA = 1.0f / SiA, invB = 1.0f / SiB;
    float invC = 1.0f / SiC, invD = 1.0f / SiD;

    // Epilogue: normalize + transpose via per-warp fp32 slab (stride 68),
    // then fp16 ILV16 stores to g_oh (pairs adjacent, uint32 stores).
    float* slab = (float*)smc + warp * 16 * 68;  // 8 * 4352 B = 34816 B
#pragma unroll
    for (int mf = 0; mf < 4; mf++)
#pragma unroll
        for (int nf = 0; nf < 2; nf++)
#pragma unroll
            for (int j = 0; j < 4; j++) {
                int ll = nf * 8 + 2 * t4 + (j & 1);
                int d = mf * 16 + rq + (j >> 1) * 8;
                float inv = (nf == 0) ? ((j & 1) ? invB : invA)
                                      : ((j & 1) ? invD : invC);
                slab[ll * 68 + d] = ot[mf][nf][j] * inv;
            }
    __syncwarp();
    {
        int ll = lane >> 1, d0 = (lane & 1) * 32;
        __half* dst = g_oh + ((size_t)h * LSEQ + l0 + warp * 16 + ll) * HD;
#pragma unroll
        for (int u = 0; u < 8; u++) {
            float4 v4 = *(const float4*)(slab + ll * 68 + d0 + u * 4);
            int d = d0 + u * 4;
            *(uint32_t*)(dst + ILV16(d)) = pack_h2(v4.x, v4.y);
            *(uint32_t*)(dst + ILV16(d + 2)) = pack_h2(v4.z, v4.w);
        }
    }
}

// ---------------------------------------------------------------------------
// Kernel 4: out = attn_out @ Wo^T + b (fp16 in, fp32 out). BM=128, BN=64.
// ---------------------------------------------------------------------------
#define OAH (128 * 48)
#define OBH (64 * 48)
__global__ void __launch_bounds__(256, 2) gemm_out(const float* __restrict__ bout,
                                                   float* __restrict__ out) {
    extern __shared__ __half smo[];
    __half* As = smo;               // [2][128*48]
    __half* Bs = smo + 2 * OAH;     // [2][64*48]
    const int tid = threadIdx.x, lane = tid & 31, warp = tid >> 5;
    const int wm = warp >> 1, wn = warp & 1;
    const int rq = lane >> 2, t4 = lane & 3;
    const int r0 = blockIdx.x * 128, c0 = blockIdx.y * 64;
    uint32_t sA = (uint32_t)__cvta_generic_to_shared(As);
    uint32_t sB = (uint32_t)__cvta_generic_to_shared(Bs);
    float acc[2][4][4] = {};

    auto prefetch = [&](int st, int kt) {
        int k0 = kt * 32;
#pragma unroll
        for (int p = 0; p < 2; p++) {
            int c = tid + p * 256;
            int row = c >> 2, off = c & 3;
            int r = r0 + row;
            int l = r >> 1, b = r & 1;
            int e = k0 + off * 8;
            int hh = e >> 6, d = e & 63;
            cp16(sA + (st * OAH + row * 48) * 2 + off * 16,
                 g_oh + ((size_t)(b * NH + hh) * LSEQ + l) * HD + d);
        }
        {
            int row = tid >> 2, off = tid & 3;
            cp16(sB + (st * OBH + row * 48) * 2 + off * 16,
                 g_woh + (size_t)(c0 + row) * EMB + k0 + off * 8);
        }
    };

    prefetch(0, 0);
    cp_commit();
    const int nk = EMB / 32;
    for (int kt = 0; kt < nk; kt++) {
        if (kt + 1 < nk) {
            prefetch((kt + 1) & 1, kt + 1);
            cp_commit();
            cp_wait1();
        } else {
            cp_wait0();
        }
        __syncthreads();
        gemm16_stage<4>(As + (kt & 1) * OAH, Bs + (kt & 1) * OBH, acc, wm, wn, rq, t4);
        __syncthreads();
    }

#pragma unroll
    for (int mf = 0; mf < 2; mf++)
#pragma unroll
        for (int nf = 0; nf < 4; nf++)
#pragma unroll
            for (int j = 0; j < 4; j++) {
                int r = r0 + wm * 32 + mf * 16 + rq + (j >> 1) * 8;
                int c = c0 + wn * 32 + nf * 8 + 2 * t4 + (j & 1);
                out[(size_t)r * EMB + c] = acc[mf][nf][j] + bout[c];
            }
}

// ---------------------------------------------------------------------------
extern "C" void kernel_launch(void* const* d_in, const int* in_sizes, int n_in,
                              void* d_out, int out_size) {
    (void)in_sizes; (void)n_in; (void)out_size;
    const float* x    = (const float*)d_in[0];
    const float* Win  = (const float*)d_in[1];
    const float* bin  = (const float*)d_in[2];
    const float* Wout = (const float*)d_in[3];
    const float* bout = (const float*)d_in[4];
    const float* Er   = (const float*)d_in[5];
    float* out = (float*)d_out;

    const int qkv_smem = 4 * QAH * sizeof(__half);                 // 49152
    const int rel_smem = (128 + 64) * 80 * sizeof(__half);         // 30720
    const int out_smem = (2 * OAH + 2 * OBH) * sizeof(__half);     // 36864

    cudaFuncSetAttribute(gemm_qkv, cudaFuncAttributeMaxDynamicSharedMemorySize, qkv_smem);
    cudaFuncSetAttribute(gemm_rel, cudaFuncAttributeMaxDynamicSharedMemorySize, rel_smem);
    cudaFuncSetAttribute(gemm_out, cudaFuncAttributeMaxDynamicSharedMemorySize, out_smem);
    cudaFuncSetAttribute(flash_attn, cudaFuncAttributeMaxDynamicSharedMemorySize, FLASH_SMEM);

    preround<<<(NX + NWI + NWO + NER) / 4 / 256, 256>>>(
        (const float4*)x, (const float4*)Win, (const float4*)Wout, (const float4*)Er);
    gemm_qkv<<<dim3(32, 12), 256, qkv_smem>>>(bin);
    gemm_rel<<<dim3(16, 32, 16), 256, rel_smem>>>();
    flash_attn<<<dim3(16, 16), 256, FLASH_SMEM>>>();
    gemm_out<<<dim3(32, 8), 256, out_smem>>>(bout, out);
}